// round 16
// baseline (speedup 1.0000x reference)
#include <cuda_runtime.h>
#include <cuda_bf16.h>
#include <cuda_fp16.h>
#include <cstdint>

#define SEQ 512
#define D   256
#define NH  8

// ---------------- scratch (device globals; no allocation) ----------------
__device__ float g_qp[SEQ * D];
__device__ __nv_bfloat16 g_qp_hi[SEQ * D];
__device__ __nv_bfloat16 g_qp_lo[SEQ * D];
__device__ __half g_P[256 * 512 * 256];              // Pk cube fp16 (67MB)
__device__ float  g_Pv[256 * 512 * 256];             // Pv cube fp32 (134MB)
__device__ __nv_bfloat16 g_a_hi[SEQ * NH * D];
__device__ __nv_bfloat16 g_a_lo[SEQ * NH * D];
__device__ __nv_bfloat16 g_k_hi[SEQ * D];
__device__ __nv_bfloat16 g_k_lo[SEQ * D];
__device__ __nv_bfloat16 g_v_hi[SEQ * D];
__device__ __nv_bfloat16 g_v_lo[SEQ * D];
__device__ float g_w[SEQ * NH * D];                  // attn-weighted v
// split-KV flash partials
__device__ float g_po[8 * 16 * 4 * 32 * 256];
__device__ float g_pm[8 * 16 * 4 * 32];
__device__ float g_pl[8 * 16 * 4 * 32];

// ---------------- helpers ----------------
__device__ __forceinline__ uint32_t smem_u32(const void* p) {
    uint32_t a;
    asm("{ .reg .u64 t; cvta.to.shared.u64 t, %1; cvt.u32.u64 %0, t; }" : "=r"(a) : "l"(p));
    return a;
}
__device__ __forceinline__ void cpa16(uint32_t s, const void* g) {
    asm volatile("cp.async.cg.shared.global [%0], [%1], 16;" :: "r"(s), "l"(g) : "memory");
}
#define CP_COMMIT() asm volatile("cp.async.commit_group;" ::: "memory")
#define CP_WAIT(n)  asm volatile("cp.async.wait_group %0;" :: "n"(n) : "memory")
__device__ __forceinline__ void ldsm_x4(uint32_t r[4], uint32_t addr) {
    asm volatile("ldmatrix.sync.aligned.m8n8.x4.shared.b16 {%0,%1,%2,%3}, [%4];"
        : "=r"(r[0]), "=r"(r[1]), "=r"(r[2]), "=r"(r[3]) : "r"(addr));
}
__device__ __forceinline__ void ldsm_x4t(uint32_t r[4], uint32_t addr) {
    asm volatile("ldmatrix.sync.aligned.m8n8.x4.trans.shared.b16 {%0,%1,%2,%3}, [%4];"
        : "=r"(r[0]), "=r"(r[1]), "=r"(r[2]), "=r"(r[3]) : "r"(addr));
}
__device__ __forceinline__ void ldsm_x2(uint32_t r[2], uint32_t addr) {
    asm volatile("ldmatrix.sync.aligned.m8n8.x2.shared.b16 {%0,%1}, [%2];"
        : "=r"(r[0]), "=r"(r[1]) : "r"(addr));
}
__device__ __forceinline__ void mma16816(float c[4], const uint32_t a[4], const uint32_t b[2]) {
    asm volatile("mma.sync.aligned.m16n8k16.row.col.f32.bf16.bf16.f32 "
        "{%0,%1,%2,%3}, {%4,%5,%6,%7}, {%8,%9}, {%0,%1,%2,%3};"
        : "+f"(c[0]), "+f"(c[1]), "+f"(c[2]), "+f"(c[3])
        : "r"(a[0]), "r"(a[1]), "r"(a[2]), "r"(a[3]), "r"(b[0]), "r"(b[1]));
}
__device__ __forceinline__ void mma16816_2(float c[4], const uint32_t a[4],
                                           uint32_t b0, uint32_t b1) {
    asm volatile("mma.sync.aligned.m16n8k16.row.col.f32.bf16.bf16.f32 "
        "{%0,%1,%2,%3}, {%4,%5,%6,%7}, {%8,%9}, {%0,%1,%2,%3};"
        : "+f"(c[0]), "+f"(c[1]), "+f"(c[2]), "+f"(c[3])
        : "r"(a[0]), "r"(a[1]), "r"(a[2]), "r"(a[3]), "r"(b0), "r"(b1));
}

// prep2: split k, v
__global__ __launch_bounds__(256, 1)
void prep2_kernel(const float* __restrict__ kin, const float* __restrict__ vin)
{
    int idx = blockIdx.x * 256 + threadIdx.x;
    for (int e = 0; e < 2; e++) {
        int l = idx * 2 + e;
        float kv = kin[l], vv = vin[l];
        __nv_bfloat16 kh = __float2bfloat16(kv), vh = __float2bfloat16(vv);
        g_k_hi[l] = kh; g_k_lo[l] = __float2bfloat16(kv - __bfloat162float(kh));
        g_v_hi[l] = vh; g_v_lo[l] = __float2bfloat16(vv - __bfloat162float(vh));
    }
}

// ============================================================
// qp = q @ Wq^T  (+ bf16 hi/lo split)
// ============================================================
__global__ __launch_bounds__(256, 1)
void qp_kernel(const float* __restrict__ q, const float* __restrict__ Wq)
{
    __shared__ float q_s[4][D];
    int i0 = blockIdx.x * 4;
    for (int idx = threadIdx.x; idx < 4 * D; idx += 256)
        q_s[idx / D][idx % D] = q[(i0 + idx / D) * D + idx % D];
    __syncthreads();

    int o = threadIdx.x;
    const float* wrow = Wq + o * D;
    float acc[4] = {0.f, 0.f, 0.f, 0.f};
    for (int m = 0; m < D; m++) {
        float wv = wrow[m];
#pragma unroll
        for (int r = 0; r < 4; r++) acc[r] += q_s[r][m] * wv;
    }
#pragma unroll
    for (int r = 0; r < 4; r++) {
        float x = acc[r];
        int off = (i0 + r) * D + o;
        g_qp[off] = x;
        __nv_bfloat16 h = __float2bfloat16(x);
        g_qp_hi[off] = h;
        g_qp_lo[off] = __float2bfloat16(x - __bfloat162float(h));
    }
}

// ============================================================
// cube_gemm: 2 CTAs/SM, 128x128 tile, warp 64x32, m=32 chunks,
//   2-stage, term-major, inline W split.
//   mode 0: fp16 cube -> g_P; mode 1: fp32 cube -> g_Pv
// ============================================================
#define RSA   80
#define ARR4  10240
#define STG   40960
#define SMEM_G (2 * STG)

__global__ __launch_bounds__(256, 2)
void cube_gemm(const float* __restrict__ W, int mode)
{
    extern __shared__ char smem[];
    uint32_t sbase = smem_u32(smem);
    int tid = threadIdx.x, lane = tid & 31, wid = tid >> 5;
    int wr = wid >> 2;
    int wc = wid & 3;

    int j  = blockIdx.x >> 3;
    int it = (blockIdx.x >> 1) & 3;
    int kh = blockIdx.x & 1;
    int i0 = it * 128;
    long jb = (long)j * 256 + kh * 128;

    const __nv_bfloat16* Ah = g_qp_hi;
    const __nv_bfloat16* Al = g_qp_lo;

    float4 wreg[4];
    int wrow = tid >> 3;
    int wf4  = tid & 7;
    auto wldg = [&](int c) {
        const float4* src = (const float4*)(W + (jb) * 256 + c * 32);
#pragma unroll
        for (int p = 0; p < 4; p++) {
            int r = p * 32 + wrow;
            wreg[p] = src[(size_t)r * 64 + wf4];
        }
    };
    auto wsts = [&](int s) {
        char* st = smem + s * STG;
#pragma unroll
        for (int p = 0; p < 4; p++) {
            int r = p * 32 + wrow;
            float4 v = wreg[p];
            __nv_bfloat16 h0 = __float2bfloat16(v.x), h1 = __float2bfloat16(v.y);
            __nv_bfloat16 h2 = __float2bfloat16(v.z), h3 = __float2bfloat16(v.w);
            union { __nv_bfloat162 b[2]; uint2 u; } hi, lo;
            hi.b[0] = __nv_bfloat162(h0, h1); hi.b[1] = __nv_bfloat162(h2, h3);
            lo.b[0] = __nv_bfloat162(__float2bfloat16(v.x - __bfloat162float(h0)),
                                     __float2bfloat16(v.y - __bfloat162float(h1)));
            lo.b[1] = __nv_bfloat162(__float2bfloat16(v.z - __bfloat162float(h2)),
                                     __float2bfloat16(v.w - __bfloat162float(h3)));
            uint32_t off = (uint32_t)(r * RSA + wf4 * 8);
            *(uint2*)(st + 2 * ARR4 + off) = hi.u;
            *(uint2*)(st + 3 * ARR4 + off) = lo.u;
        }
    };
    auto loadA = [&](int c, int s) {
        uint32_t st = sbase + s * STG;
        int m0 = c * 32;
#pragma unroll
        for (int p = 0; p < 2; p++) {
            int idx = p * 256 + tid;
            int r = idx >> 2, ss = idx & 3;
            uint32_t so = (uint32_t)(r * RSA + ss * 16);
            cpa16(st + so,        Ah + (i0 + r) * 256 + m0 + ss * 8);
            cpa16(st + ARR4 + so, Al + (i0 + r) * 256 + m0 + ss * 8);
        }
        CP_COMMIT();
    };

    float acc[4][4][4];
#pragma unroll
    for (int mt = 0; mt < 4; mt++)
#pragma unroll
        for (int nt = 0; nt < 4; nt++)
#pragma unroll
            for (int e = 0; e < 4; e++) acc[mt][nt][e] = 0.f;

    wldg(0);
    loadA(0, 0);
    loadA(1, 1);
    wsts(0);
    wldg(1); wsts(1);
    wldg(2);

    uint32_t bAddrOff = (uint32_t)((wc * 32 + ((lane >> 4) * 8) + (lane & 7)) * RSA
                      + ((lane >> 3) & 1) * 16);
    uint32_t aAddrOff = (uint32_t)((wr * 64 + (lane & 15)) * RSA + (lane >> 4) * 16);

    for (int c = 0; c < 8; c++) {
        if (c < 7) CP_WAIT(1); else CP_WAIT(0);
        __syncthreads();
        uint32_t st  = sbase + (c & 1) * STG;
#pragma unroll
        for (int ks = 0; ks < 2; ks++) {
            uint32_t bh[4][2], bl[4][2];
#pragma unroll
            for (int ntp = 0; ntp < 2; ntp++) {
                uint32_t bo = st + 2 * ARR4 + bAddrOff + ntp * 16 * RSA + ks * 32;
                uint32_t t4[4];
                ldsm_x4(t4, bo);
                bh[ntp * 2][0] = t4[0]; bh[ntp * 2][1] = t4[1];
                bh[ntp * 2 + 1][0] = t4[2]; bh[ntp * 2 + 1][1] = t4[3];
                ldsm_x4(t4, bo + ARR4);
                bl[ntp * 2][0] = t4[0]; bl[ntp * 2][1] = t4[1];
                bl[ntp * 2 + 1][0] = t4[2]; bl[ntp * 2 + 1][1] = t4[3];
            }
#pragma unroll
            for (int mtp = 0; mtp < 2; mtp++) {
                uint32_t ah[2][4], al[2][4];
#pragma unroll
                for (int q2 = 0; q2 < 2; q2++) {
                    uint32_t ao = st + aAddrOff + (mtp * 2 + q2) * 16 * RSA + ks * 32;
                    ldsm_x4(ah[q2], ao);
                    ldsm_x4(al[q2], ao + ARR4);
                }
#pragma unroll
                for (int q2 = 0; q2 < 2; q2++)
#pragma unroll
                    for (int nt = 0; nt < 4; nt++)
                        mma16816(acc[mtp * 2 + q2][nt], ah[q2], bh[nt]);
#pragma unroll
                for (int q2 = 0; q2 < 2; q2++)
#pragma unroll
                    for (int nt = 0; nt < 4; nt++)
                        mma16816(acc[mtp * 2 + q2][nt], ah[q2], bl[nt]);
#pragma unroll
                for (int q2 = 0; q2 < 2; q2++)
#pragma unroll
                    for (int nt = 0; nt < 4; nt++)
                        mma16816(acc[mtp * 2 + q2][nt], al[q2], bh[nt]);
            }
        }
        __syncthreads();
        if (c + 2 < 8) {
            loadA(c + 2, c & 1);
            wsts(c & 1);
            if (c + 3 < 8) wldg(c + 3);
        }
    }

    int g = lane >> 2, qq = lane & 3;
    if (mode == 0) {
#pragma unroll
        for (int mt = 0; mt < 4; mt++) {
            int ir = i0 + wr * 64 + mt * 16 + g;
            __half* base0 = g_P + ((size_t)j * 512 + ir) * 256;
            __half* base1 = base0 + 8 * 256;
#pragma unroll
            for (int nt = 0; nt < 4; nt++) {
                int kk = kh * 128 + wc * 32 + nt * 8 + qq * 2;
                *(__half2*)(base0 + kk) = __floats2half2_rn(acc[mt][nt][0], acc[mt][nt][1]);
                *(__half2*)(base1 + kk) = __floats2half2_rn(acc[mt][nt][2], acc[mt][nt][3]);
            }
        }
    } else {
#pragma unroll
        for (int mt = 0; mt < 4; mt++) {
            int ir = i0 + wr * 64 + mt * 16 + g;
            float* base0 = g_Pv + ((size_t)j * 512 + ir) * 256;
            float* base1 = base0 + 8 * 256;
#pragma unroll
            for (int nt = 0; nt < 4; nt++) {
                int kk = kh * 128 + wc * 32 + nt * 8 + qq * 2;
                *(float2*)(base0 + kk) = make_float2(acc[mt][nt][0], acc[mt][nt][1]);
                *(float2*)(base1 + kk) = make_float2(acc[mt][nt][2], acc[mt][nt][3]);
            }
        }
    }
}

// ============================================================
// vfold: out[i,j] = sum_k Pv[j][i][k] * w[i, j>>5, k]
// grid 4096 = i*8+n, 256 threads; warp handles 4 j
// ============================================================
__global__ __launch_bounds__(256, 1)
void vfold_kernel(float* __restrict__ out)
{
    __shared__ float w_s[256];
    int i = blockIdx.x >> 3;
    int n = blockIdx.x & 7;
    int tid = threadIdx.x, lane = tid & 31, wid = tid >> 5;
    w_s[tid] = g_w[((size_t)i * NH + n) * 256 + tid];
    __syncthreads();

    float4 w0 = *(const float4*)(w_s + lane * 8);
    float4 w1 = *(const float4*)(w_s + lane * 8 + 4);
#pragma unroll
    for (int q = 0; q < 4; q++) {
        int j = n * 32 + wid * 4 + q;
        const float4* p = (const float4*)(g_Pv + ((size_t)j * 512 + i) * 256) + lane * 2;
        float4 p0 = p[0], p1 = p[1];
        float s = w0.x * p0.x + w0.y * p0.y + w0.z * p0.z + w0.w * p0.w
                + w1.x * p1.x + w1.y * p1.y + w1.z * p1.z + w1.w * p1.w;
#pragma unroll
        for (int off = 16; off > 0; off >>= 1)
            s += __shfl_xor_sync(0xffffffffu, s, off);
        if (lane == 0) out[(size_t)i * 256 + j] = s;
    }
}

// ============================================================
// kfold (fp16 P)
// ============================================================
__global__ __launch_bounds__(128, 1)
void kfold_kernel()
{
    __shared__ float qs[32];
    int i = blockIdx.x >> 3;
    int n = blockIdx.x & 7;
    int tid = threadIdx.x;
    if (tid < 32) qs[tid] = g_qp[i * 256 + n * 32 + tid];
    __syncthreads();

    const __half2* base = (const __half2*)g_P
                        + ((size_t)(n * 32) * 512 + i) * 128 + tid;
    float ax = 0.f, ay = 0.f;
#pragma unroll 8
    for (int jj = 0; jj < 32; jj++) {
        float2 p = __half22float2(base[(size_t)jj * 65536]);
        float s = qs[jj];
        ax += s * p.x; ay += s * p.y;
    }
    const float rs = 0.04419417382415922f;
    ax *= rs; ay *= rs;
    __nv_bfloat16 hx = __float2bfloat16(ax);
    __nv_bfloat16 hy = __float2bfloat16(ay);
    __nv_bfloat16 lx = __float2bfloat16(ax - __bfloat162float(hx));
    __nv_bfloat16 ly = __float2bfloat16(ay - __bfloat162float(hy));
    size_t o = ((size_t)i * NH + n) * 128 + tid;
    ((__nv_bfloat162*)g_a_hi)[o] = __nv_bfloat162(hx, hy);
    ((__nv_bfloat162*)g_a_lo)[o] = __nv_bfloat162(lx, ly);
}

// ============================================================
// flash_part v2 (occ 2): K chunks m=32, V in 4 quarters
// ============================================================
#define FA_A_HI  0
#define FA_A_LO  16896
#define FA_KBUF  33792
#define FA_KSTG  20480
#define FA_VLO   16896
#define FA_P     74752
#define FA_PLO   8704
#define FA_STATS 92160
#define SMEM_FA  93696

__global__ __launch_bounds__(256, 2)
void flash_part()
{
    extern __shared__ char smem[];
    uint32_t sb = smem_u32(smem);
    int tid = threadIdx.x, lane = tid & 31, wid = tid >> 5;
    int wi = wid & 1, wh = wid >> 1;

    int n = blockIdx.x / 40;
    int r = blockIdx.x % 40;
    int b, c;
    if      (r < 4)  { b = r;                c = 0;            }
    else if (r < 12) { b = 4 + (r - 4) / 2;  c = (r - 4) % 2;  }
    else if (r < 24) { b = 8 + (r - 12) / 3; c = (r - 12) % 3; }
    else             { b = 12 + (r - 24) / 4; c = (r - 24) % 4; }
    int i0 = b * 32;
    int t0 = c * 128;
    bool lastc = (c == (b >> 2));

    float* sMaxP = (float*)(smem + FA_STATS);
    float* sSumP = sMaxP + 128;

#pragma unroll
    for (int p = 0; p < 4; p++) {
        int idx = p * 256 + tid;
        int rr = idx >> 5, cc = idx & 31;
        cpa16(sb + FA_A_HI + rr * 528 + cc * 16, g_a_hi + ((size_t)(i0 + rr) * NH + n) * 256 + cc * 8);
        cpa16(sb + FA_A_LO + rr * 528 + cc * 16, g_a_lo + ((size_t)(i0 + rr) * NH + n) * 256 + cc * 8);
    }
    CP_COMMIT();

    auto kload = [&](int mc, int s) {
        uint32_t st = sb + FA_KBUF + s * FA_KSTG;
#pragma unroll
        for (int p = 0; p < 2; p++) {
            int idx = p * 256 + tid;
            int rr = idx >> 2, cc = idx & 3;
            cpa16(st + rr * 80 + cc * 16,         g_k_hi + (t0 + rr) * 256 + mc * 32 + cc * 8);
            cpa16(st + 10240 + rr * 80 + cc * 16, g_k_lo + (t0 + rr) * 256 + mc * 32 + cc * 8);
        }
        CP_COMMIT();
    };
    auto vload = [&](int tq) {
        uint32_t st = sb + FA_KBUF;
#pragma unroll
        for (int p = 0; p < 4; p++) {
            int idx = p * 256 + tid;
            int rr = idx >> 5, cc = idx & 31;
            cpa16(st + rr * 528 + cc * 16,          g_v_hi + (t0 + tq * 32 + rr) * 256 + cc * 8);
            cpa16(st + FA_VLO + rr * 528 + cc * 16, g_v_lo + (t0 + tq * 32 + rr) * 256 + cc * 8);
        }
        CP_COMMIT();
    };

    kload(0, 0);
    kload(1, 1);

    int g = lane >> 2, qq = lane & 3;
    float s[4][4];
#pragma unroll
    for (int nt = 0; nt < 4; nt++)
#pragma unroll
        for (int e = 0; e < 4; e++) s[nt][e] = 0.f;

    for (int mc = 0; mc < 8; mc++) {
        if (mc < 7) CP_WAIT(1); else CP_WAIT(0);
        __syncthreads();
        uint32_t kb = sb + FA_KBUF + (mc & 1) * FA_KSTG;
        uint32_t aH = sb + FA_A_HI + (wi * 16 + (lane & 15)) * 528
                    + (lane >> 4) * 16 + mc * 64;
#pragma unroll
        for (int ks = 0; ks < 2; ks++) {
            uint32_t ah[4], al[4];
            ldsm_x4(ah, aH + ks * 32);
            ldsm_x4(al, aH + (FA_A_LO - FA_A_HI) + ks * 32);
#pragma unroll
            for (int nt = 0; nt < 4; nt++) {
                uint32_t bo = kb + (wh * 32 + nt * 8 + (lane & 7)) * 80
                            + ((lane >> 3) & 1) * 16 + ks * 32;
                uint32_t bh[2], bl[2];
                ldsm_x2(bh, bo);
                ldsm_x2(bl, bo + 10240);
                mma16816(s[nt], ah, bh);
                mma16816(s[nt], ah, bl);
                mma16816(s[nt], al, bh);
            }
        }
        __syncthreads();
        if (mc < 6) kload(mc + 2, mc & 1);
    }

    if (lastc) {
#pragma unroll
        for (int nt = 0; nt < 4; nt++) {
            int tbase = t0 + wh * 32 + nt * 8 + qq * 2;
            int ig0 = i0 + wi * 16 + g, ig1 = ig0 + 8;
            if (tbase     > ig0) s[nt][0] = -1e30f;
            if (tbase + 1 > ig0) s[nt][1] = -1e30f;
            if (tbase     > ig1) s[nt][2] = -1e30f;
            if (tbase + 1 > ig1) s[nt][3] = -1e30f;
        }
    }

    float mx0 = -1e30f, mx1 = -1e30f;
#pragma unroll
    for (int nt = 0; nt < 4; nt++) {
        mx0 = fmaxf(mx0, fmaxf(s[nt][0], s[nt][1]));
        mx1 = fmaxf(mx1, fmaxf(s[nt][2], s[nt][3]));
    }
#pragma unroll
    for (int off = 1; off <= 2; off <<= 1) {
        mx0 = fmaxf(mx0, __shfl_xor_sync(0xffffffffu, mx0, off));
        mx1 = fmaxf(mx1, __shfl_xor_sync(0xffffffffu, mx1, off));
    }
    if (qq == 0) {
        sMaxP[wh * 32 + wi * 16 + g]     = mx0;
        sMaxP[wh * 32 + wi * 16 + g + 8] = mx1;
    }
    __syncthreads();

    int r0 = wi * 16 + g, r1 = r0 + 8;
    float mn0 = fmaxf(fmaxf(sMaxP[r0], sMaxP[32 + r0]),
                      fmaxf(sMaxP[64 + r0], sMaxP[96 + r0]));
    float mn1 = fmaxf(fmaxf(sMaxP[r1], sMaxP[32 + r1]),
                      fmaxf(sMaxP[64 + r1], sMaxP[96 + r1]));

    float sum0 = 0.f, sum1 = 0.f;
#pragma unroll
    for (int nt = 0; nt < 4; nt++) {
        float p0 = __expf(s[nt][0] - mn0);
        float p1 = __expf(s[nt][1] - mn0);
        float p2 = __expf(s[nt][2] - mn1);
        float p3 = __expf(s[nt][3] - mn1);
        sum0 += p0 + p1; sum1 += p2 + p3;
        __nv_bfloat16 h0 = __float2bfloat16(p0), h1 = __float2bfloat16(p1);
        __nv_bfloat16 h2 = __float2bfloat16(p2), h3 = __float2bfloat16(p3);
        __nv_bfloat162 lo01(__float2bfloat16(p0 - __bfloat162float(h0)),
                            __float2bfloat16(p1 - __bfloat162float(h1)));
        __nv_bfloat162 lo23(__float2bfloat16(p2 - __bfloat162float(h2)),
                            __float2bfloat16(p3 - __bfloat162float(h3)));
        uint32_t colb = (wh * 32 + nt * 8 + qq * 2) * 2;
        *(__nv_bfloat162*)(smem + FA_P + r0 * 272 + colb) = __nv_bfloat162(h0, h1);
        *(__nv_bfloat162*)(smem + FA_P + r1 * 272 + colb) = __nv_bfloat162(h2, h3);
        *(__nv_bfloat162*)(smem + FA_P + FA_PLO + r0 * 272 + colb) = lo01;
        *(__nv_bfloat162*)(smem + FA_P + FA_PLO + r1 * 272 + colb) = lo23;
    }
#pragma unroll
    for (int off = 1; off <= 2; off <<= 1) {
        sum0 += __shfl_xor_sync(0xffffffffu, sum0, off);
        sum1 += __shfl_xor_sync(0xffffffffu, sum1, off);
    }
    if (qq == 0) {
        sSumP[wh * 32 + r0] = sum0;
        sSumP[wh * 32 + r1] = sum1;
    }
    __syncthreads();

    int pidx = (n * 16 + b) * 4 + c;
    if (tid < 32) {
        float mn = fmaxf(fmaxf(sMaxP[tid], sMaxP[32 + tid]),
                         fmaxf(sMaxP[64 + tid], sMaxP[96 + tid]));
        float l = sSumP[tid] + sSumP[32 + tid] + sSumP[64 + tid] + sSumP[96 + tid];
        g_pm[pidx * 32 + tid] = mn;
        g_pl[pidx * 32 + tid] = l;
    }
    vload(0);
    __syncthreads();

    float O[8][4];
#pragma unroll
    for (int t = 0; t < 8; t++)
#pragma unroll
        for (int e = 0; e < 4; e++) O[t][e] = 0.f;

    for (int tq = 0; tq < 4; tq++) {
        CP_WAIT(0);
        __syncthreads();
#pragma unroll
        for (int ks = 0; ks < 2; ks++) {
            uint32_t pa = sb + FA_P + (wi * 16 + (lane & 15)) * 272
                        + (lane >> 4) * 16 + tq * 64 + ks * 32;
            uint32_t ph[4], pl[4];
            ldsm_x4(ph, pa);
            ldsm_x4(pl, pa + FA_PLO);
#pragma unroll
            for (int ntp = 0; ntp < 4; ntp++) {
                uint32_t vo = sb + FA_KBUF + (ks * 16 + (lane & 15)) * 528
                            + (wh * 64 + ntp * 16 + (lane >> 4) * 8) * 2;
                uint32_t vh[4], vl[4];
                ldsm_x4t(vh, vo);
                ldsm_x4t(vl, vo + FA_VLO);
                mma16816_2(O[ntp * 2],     ph, vh[0], vh[1]);
                mma16816_2(O[ntp * 2],     ph, vl[0], vl[1]);
                mma16816_2(O[ntp * 2],     pl, vh[0], vh[1]);
                mma16816_2(O[ntp * 2 + 1], ph, vh[2], vh[3]);
                mma16816_2(O[ntp * 2 + 1], ph, vl[2], vl[3]);
                mma16816_2(O[ntp * 2 + 1], pl, vh[2], vh[3]);
            }
        }
        __syncthreads();
        if (tq < 3) vload(tq + 1);
    }

    float* po = g_po + (size_t)pidx * 32 * 256;
#pragma unroll
    for (int knt = 0; knt < 8; knt++) {
        int k = wh * 64 + knt * 8 + qq * 2;
        *(float2*)&po[(size_t)r0 * 256 + k] = make_float2(O[knt][0], O[knt][1]);
        *(float2*)&po[(size_t)r1 * 256 + k] = make_float2(O[knt][2], O[knt][3]);
    }
}

// flash_combine: merge <=4 chunks per (n, b) -> g_w
__global__ __launch_bounds__(256, 1)
void flash_combine()
{
    int bx = blockIdx.x;
    int n = bx >> 4, b = bx & 15;
    int nch = (b >> 2) + 1;
    int tid = threadIdx.x;
    int row = tid >> 3;
    int k0 = (tid & 7) * 32;

    float m = -1e30f;
#pragma unroll 4
    for (int c = 0; c < nch; c++)
        m = fmaxf(m, g_pm[(bx * 4 + c) * 32 + row]);

    float acc[32];
#pragma unroll
    for (int e = 0; e < 32; e++) acc[e] = 0.f;
    float l = 0.f;

    for (int c = 0; c < nch; c++) {
        float f = __expf(g_pm[(bx * 4 + c) * 32 + row] - m);
        l += f * g_pl[(bx * 4 + c) * 32 + row];
        const float4* po = (const float4*)(g_po + ((size_t)(bx * 4 + c) * 32 + row) * 256 + k0);
#pragma unroll
        for (int e = 0; e < 8; e++) {
            float4 v = po[e];
            acc[e * 4 + 0] += f * v.x; acc[e * 4 + 1] += f * v.y;
            acc[e * 4 + 2] += f * v.z; acc[e * 4 + 3] += f * v.w;
        }
    }
    float il = 1.f / l;
    float* wp = g_w + ((size_t)(b * 32 + row) * NH + n) * 256 + k0;
#pragma unroll
    for (int e = 0; e < 8; e++) {
        *(float4*)(wp + e * 4) = make_float4(acc[e * 4 + 0] * il, acc[e * 4 + 1] * il,
                                             acc[e * 4 + 2] * il, acc[e * 4 + 3] * il);
    }
}

// ============================================================
extern "C" void kernel_launch(void* const* d_in, const int* in_sizes, int n_in,
                              void* d_out, int out_size)
{
    const float* q   = (const float*)d_in[0];
    const float* kk  = (const float*)d_in[1];
    const float* vv  = (const float*)d_in[2];
    const float* Wq  = (const float*)d_in[3];
    const float* Wk  = (const float*)d_in[4];
    const float* Wv  = (const float*)d_in[5];
    float* out = (float*)d_out;

    static cudaStream_t sB = nullptr;
    static cudaEvent_t evA = nullptr, evB = nullptr;
    if (!sB) {
        cudaStreamCreateWithFlags(&sB, cudaStreamNonBlocking);
        cudaEventCreateWithFlags(&evA, cudaEventDisableTiming);
        cudaEventCreateWithFlags(&evB, cudaEventDisableTiming);
    }

    cudaFuncSetAttribute(cube_gemm,  cudaFuncAttributeMaxDynamicSharedMemorySize, SMEM_G);
    cudaFuncSetAttribute(flash_part, cudaFuncAttributeMaxDynamicSharedMemorySize, SMEM_FA);

    prep2_kernel<<<256, 256>>>(kk, vv);
    qp_kernel<<<SEQ / 4, 256>>>(q, Wq);
    cube_gemm<<<2048, 256, SMEM_G>>>(Wk, 0);           // Pk cube (fp16)
    cudaEventRecord(evA, 0);
    cudaStreamWaitEvent(sB, evA, 0);
    cube_gemm<<<2048, 256, SMEM_G, sB>>>(Wv, 1);       // Pv cube (fp32) on stream B
    cudaEventRecord(evB, sB);
    kfold_kernel<<<4096, 128>>>();                     // legacy, overlaps gemm2
    flash_part<<<320, 256, SMEM_FA>>>();
    flash_combine<<<128, 256>>>();                     // -> g_w
    cudaStreamWaitEvent(0, evB, 0);
    vfold_kernel<<<4096, 256>>>(out);                  // -> out
}

// round 17
// speedup vs baseline: 1.0010x; 1.0010x over previous
#include <cuda_runtime.h>
#include <cuda_bf16.h>
#include <cuda_fp16.h>
#include <cstdint>

#define SEQ 512
#define D   256
#define NH  8

// ---------------- scratch (device globals; no allocation) ----------------
__device__ float g_qp[SEQ * D];
__device__ __nv_bfloat16 g_qp_hi[SEQ * D];
__device__ __nv_bfloat16 g_qp_lo[SEQ * D];
__device__ __half g_P[256 * 512 * 256];              // Pk cube fp16 (67MB)
__device__ float  g_Pv[256 * 512 * 256];             // Pv cube fp32 (134MB)
__device__ __nv_bfloat16 g_a_hi[SEQ * NH * D];
__device__ __nv_bfloat16 g_a_lo[SEQ * NH * D];
__device__ __nv_bfloat16 g_k_hi[SEQ * D];
__device__ __nv_bfloat16 g_k_lo[SEQ * D];
__device__ __nv_bfloat16 g_v_hi[SEQ * D];
__device__ __nv_bfloat16 g_v_lo[SEQ * D];
__device__ float g_w[SEQ * NH * D];                  // attn-weighted v
// split-KV flash partials
__device__ float g_po[8 * 16 * 4 * 32 * 256];
__device__ float g_pm[8 * 16 * 4 * 32];
__device__ float g_pl[8 * 16 * 4 * 32];

// ---------------- helpers ----------------
__device__ __forceinline__ uint32_t smem_u32(const void* p) {
    uint32_t a;
    asm("{ .reg .u64 t; cvta.to.shared.u64 t, %1; cvt.u32.u64 %0, t; }" : "=r"(a) : "l"(p));
    return a;
}
__device__ __forceinline__ void cpa16(uint32_t s, const void* g) {
    asm volatile("cp.async.cg.shared.global [%0], [%1], 16;" :: "r"(s), "l"(g) : "memory");
}
#define CP_COMMIT() asm volatile("cp.async.commit_group;" ::: "memory")
#define CP_WAIT(n)  asm volatile("cp.async.wait_group %0;" :: "n"(n) : "memory")
__device__ __forceinline__ void ldsm_x4(uint32_t r[4], uint32_t addr) {
    asm volatile("ldmatrix.sync.aligned.m8n8.x4.shared.b16 {%0,%1,%2,%3}, [%4];"
        : "=r"(r[0]), "=r"(r[1]), "=r"(r[2]), "=r"(r[3]) : "r"(addr));
}
__device__ __forceinline__ void ldsm_x4t(uint32_t r[4], uint32_t addr) {
    asm volatile("ldmatrix.sync.aligned.m8n8.x4.trans.shared.b16 {%0,%1,%2,%3}, [%4];"
        : "=r"(r[0]), "=r"(r[1]), "=r"(r[2]), "=r"(r[3]) : "r"(addr));
}
__device__ __forceinline__ void ldsm_x2(uint32_t r[2], uint32_t addr) {
    asm volatile("ldmatrix.sync.aligned.m8n8.x2.shared.b16 {%0,%1}, [%2];"
        : "=r"(r[0]), "=r"(r[1]) : "r"(addr));
}
__device__ __forceinline__ void mma16816(float c[4], const uint32_t a[4], const uint32_t b[2]) {
    asm volatile("mma.sync.aligned.m16n8k16.row.col.f32.bf16.bf16.f32 "
        "{%0,%1,%2,%3}, {%4,%5,%6,%7}, {%8,%9}, {%0,%1,%2,%3};"
        : "+f"(c[0]), "+f"(c[1]), "+f"(c[2]), "+f"(c[3])
        : "r"(a[0]), "r"(a[1]), "r"(a[2]), "r"(a[3]), "r"(b[0]), "r"(b[1]));
}
__device__ __forceinline__ void mma16816_2(float c[4], const uint32_t a[4],
                                           uint32_t b0, uint32_t b1) {
    asm volatile("mma.sync.aligned.m16n8k16.row.col.f32.bf16.bf16.f32 "
        "{%0,%1,%2,%3}, {%4,%5,%6,%7}, {%8,%9}, {%0,%1,%2,%3};"
        : "+f"(c[0]), "+f"(c[1]), "+f"(c[2]), "+f"(c[3])
        : "r"(a[0]), "r"(a[1]), "r"(a[2]), "r"(a[3]), "r"(b0), "r"(b1));
}

// prep2: split k, v
__global__ __launch_bounds__(256, 1)
void prep2_kernel(const float* __restrict__ kin, const float* __restrict__ vin)
{
    int idx = blockIdx.x * 256 + threadIdx.x;
    for (int e = 0; e < 2; e++) {
        int l = idx * 2 + e;
        float kv = kin[l], vv = vin[l];
        __nv_bfloat16 kh = __float2bfloat16(kv), vh = __float2bfloat16(vv);
        g_k_hi[l] = kh; g_k_lo[l] = __float2bfloat16(kv - __bfloat162float(kh));
        g_v_hi[l] = vh; g_v_lo[l] = __float2bfloat16(vv - __bfloat162float(vh));
    }
}

// ============================================================
// qp = q @ Wq^T  (+ bf16 hi/lo split)
// ============================================================
__global__ __launch_bounds__(256, 1)
void qp_kernel(const float* __restrict__ q, const float* __restrict__ Wq)
{
    __shared__ float q_s[4][D];
    int i0 = blockIdx.x * 4;
    for (int idx = threadIdx.x; idx < 4 * D; idx += 256)
        q_s[idx / D][idx % D] = q[(i0 + idx / D) * D + idx % D];
    __syncthreads();

    int o = threadIdx.x;
    const float* wrow = Wq + o * D;
    float acc[4] = {0.f, 0.f, 0.f, 0.f};
    for (int m = 0; m < D; m++) {
        float wv = wrow[m];
#pragma unroll
        for (int r = 0; r < 4; r++) acc[r] += q_s[r][m] * wv;
    }
#pragma unroll
    for (int r = 0; r < 4; r++) {
        float x = acc[r];
        int off = (i0 + r) * D + o;
        g_qp[off] = x;
        __nv_bfloat16 h = __float2bfloat16(x);
        g_qp_hi[off] = h;
        g_qp_lo[off] = __float2bfloat16(x - __bfloat162float(h));
    }
}

// ============================================================
// cube_gemm: 2 CTAs/SM, 128x128 tile, warp 64x32, m=32 chunks,
//   2-stage, term-major, inline W split.
//   mode 0: fp16 cube -> g_P; mode 1: fp32 cube -> g_Pv
// ============================================================
#define RSA   80
#define ARR4  10240
#define STG   40960
#define SMEM_G (2 * STG)

__global__ __launch_bounds__(256, 2)
void cube_gemm(const float* __restrict__ W, int mode)
{
    extern __shared__ char smem[];
    uint32_t sbase = smem_u32(smem);
    int tid = threadIdx.x, lane = tid & 31, wid = tid >> 5;
    int wr = wid >> 2;
    int wc = wid & 3;

    int j  = blockIdx.x >> 3;
    int it = (blockIdx.x >> 1) & 3;
    int kh = blockIdx.x & 1;
    int i0 = it * 128;
    long jb = (long)j * 256 + kh * 128;

    const __nv_bfloat16* Ah = g_qp_hi;
    const __nv_bfloat16* Al = g_qp_lo;

    float4 wreg[4];
    int wrow = tid >> 3;
    int wf4  = tid & 7;
    auto wldg = [&](int c) {
        const float4* src = (const float4*)(W + (jb) * 256 + c * 32);
#pragma unroll
        for (int p = 0; p < 4; p++) {
            int r = p * 32 + wrow;
            wreg[p] = src[(size_t)r * 64 + wf4];
        }
    };
    auto wsts = [&](int s) {
        char* st = smem + s * STG;
#pragma unroll
        for (int p = 0; p < 4; p++) {
            int r = p * 32 + wrow;
            float4 v = wreg[p];
            __nv_bfloat16 h0 = __float2bfloat16(v.x), h1 = __float2bfloat16(v.y);
            __nv_bfloat16 h2 = __float2bfloat16(v.z), h3 = __float2bfloat16(v.w);
            union { __nv_bfloat162 b[2]; uint2 u; } hi, lo;
            hi.b[0] = __nv_bfloat162(h0, h1); hi.b[1] = __nv_bfloat162(h2, h3);
            lo.b[0] = __nv_bfloat162(__float2bfloat16(v.x - __bfloat162float(h0)),
                                     __float2bfloat16(v.y - __bfloat162float(h1)));
            lo.b[1] = __nv_bfloat162(__float2bfloat16(v.z - __bfloat162float(h2)),
                                     __float2bfloat16(v.w - __bfloat162float(h3)));
            uint32_t off = (uint32_t)(r * RSA + wf4 * 8);
            *(uint2*)(st + 2 * ARR4 + off) = hi.u;
            *(uint2*)(st + 3 * ARR4 + off) = lo.u;
        }
    };
    auto loadA = [&](int c, int s) {
        uint32_t st = sbase + s * STG;
        int m0 = c * 32;
#pragma unroll
        for (int p = 0; p < 2; p++) {
            int idx = p * 256 + tid;
            int r = idx >> 2, ss = idx & 3;
            uint32_t so = (uint32_t)(r * RSA + ss * 16);
            cpa16(st + so,        Ah + (i0 + r) * 256 + m0 + ss * 8);
            cpa16(st + ARR4 + so, Al + (i0 + r) * 256 + m0 + ss * 8);
        }
        CP_COMMIT();
    };

    float acc[4][4][4];
#pragma unroll
    for (int mt = 0; mt < 4; mt++)
#pragma unroll
        for (int nt = 0; nt < 4; nt++)
#pragma unroll
            for (int e = 0; e < 4; e++) acc[mt][nt][e] = 0.f;

    wldg(0);
    loadA(0, 0);
    loadA(1, 1);
    wsts(0);
    wldg(1); wsts(1);
    wldg(2);

    uint32_t bAddrOff = (uint32_t)((wc * 32 + ((lane >> 4) * 8) + (lane & 7)) * RSA
                      + ((lane >> 3) & 1) * 16);
    uint32_t aAddrOff = (uint32_t)((wr * 64 + (lane & 15)) * RSA + (lane >> 4) * 16);

    for (int c = 0; c < 8; c++) {
        if (c < 7) CP_WAIT(1); else CP_WAIT(0);
        __syncthreads();
        uint32_t st  = sbase + (c & 1) * STG;
#pragma unroll
        for (int ks = 0; ks < 2; ks++) {
            uint32_t bh[4][2], bl[4][2];
#pragma unroll
            for (int ntp = 0; ntp < 2; ntp++) {
                uint32_t bo = st + 2 * ARR4 + bAddrOff + ntp * 16 * RSA + ks * 32;
                uint32_t t4[4];
                ldsm_x4(t4, bo);
                bh[ntp * 2][0] = t4[0]; bh[ntp * 2][1] = t4[1];
                bh[ntp * 2 + 1][0] = t4[2]; bh[ntp * 2 + 1][1] = t4[3];
                ldsm_x4(t4, bo + ARR4);
                bl[ntp * 2][0] = t4[0]; bl[ntp * 2][1] = t4[1];
                bl[ntp * 2 + 1][0] = t4[2]; bl[ntp * 2 + 1][1] = t4[3];
            }
#pragma unroll
            for (int mtp = 0; mtp < 2; mtp++) {
                uint32_t ah[2][4], al[2][4];
#pragma unroll
                for (int q2 = 0; q2 < 2; q2++) {
                    uint32_t ao = st + aAddrOff + (mtp * 2 + q2) * 16 * RSA + ks * 32;
                    ldsm_x4(ah[q2], ao);
                    ldsm_x4(al[q2], ao + ARR4);
                }
#pragma unroll
                for (int q2 = 0; q2 < 2; q2++)
#pragma unroll
                    for (int nt = 0; nt < 4; nt++)
                        mma16816(acc[mtp * 2 + q2][nt], ah[q2], bh[nt]);
#pragma unroll
                for (int q2 = 0; q2 < 2; q2++)
#pragma unroll
                    for (int nt = 0; nt < 4; nt++)
                        mma16816(acc[mtp * 2 + q2][nt], ah[q2], bl[nt]);
#pragma unroll
                for (int q2 = 0; q2 < 2; q2++)
#pragma unroll
                    for (int nt = 0; nt < 4; nt++)
                        mma16816(acc[mtp * 2 + q2][nt], al[q2], bh[nt]);
            }
        }
        __syncthreads();
        if (c + 2 < 8) {
            loadA(c + 2, c & 1);
            wsts(c & 1);
            if (c + 3 < 8) wldg(c + 3);
        }
    }

    int g = lane >> 2, qq = lane & 3;
    if (mode == 0) {
#pragma unroll
        for (int mt = 0; mt < 4; mt++) {
            int ir = i0 + wr * 64 + mt * 16 + g;
            __half* base0 = g_P + ((size_t)j * 512 + ir) * 256;
            __half* base1 = base0 + 8 * 256;
#pragma unroll
            for (int nt = 0; nt < 4; nt++) {
                int kk = kh * 128 + wc * 32 + nt * 8 + qq * 2;
                *(__half2*)(base0 + kk) = __floats2half2_rn(acc[mt][nt][0], acc[mt][nt][1]);
                *(__half2*)(base1 + kk) = __floats2half2_rn(acc[mt][nt][2], acc[mt][nt][3]);
            }
        }
    } else {
#pragma unroll
        for (int mt = 0; mt < 4; mt++) {
            int ir = i0 + wr * 64 + mt * 16 + g;
            float* base0 = g_Pv + ((size_t)j * 512 + ir) * 256;
            float* base1 = base0 + 8 * 256;
#pragma unroll
            for (int nt = 0; nt < 4; nt++) {
                int kk = kh * 128 + wc * 32 + nt * 8 + qq * 2;
                *(float2*)(base0 + kk) = make_float2(acc[mt][nt][0], acc[mt][nt][1]);
                *(float2*)(base1 + kk) = make_float2(acc[mt][nt][2], acc[mt][nt][3]);
            }
        }
    }
}

// ============================================================
// vfold: out[i,j] = sum_k Pv[j][i][k] * w[i, j>>5, k]
// grid 4096 = i*8+n, 256 threads; warp handles 4 j
// ============================================================
__global__ __launch_bounds__(256, 1)
void vfold_kernel(float* __restrict__ out)
{
    __shared__ float w_s[256];
    int i = blockIdx.x >> 3;
    int n = blockIdx.x & 7;
    int tid = threadIdx.x, lane = tid & 31, wid = tid >> 5;
    w_s[tid] = g_w[((size_t)i * NH + n) * 256 + tid];
    __syncthreads();

    float4 w0 = *(const float4*)(w_s + lane * 8);
    float4 w1 = *(const float4*)(w_s + lane * 8 + 4);
#pragma unroll
    for (int q = 0; q < 4; q++) {
        int j = n * 32 + wid * 4 + q;
        const float4* p = (const float4*)(g_Pv + ((size_t)j * 512 + i) * 256) + lane * 2;
        float4 p0 = p[0], p1 = p[1];
        float s = w0.x * p0.x + w0.y * p0.y + w0.z * p0.z + w0.w * p0.w
                + w1.x * p1.x + w1.y * p1.y + w1.z * p1.z + w1.w * p1.w;
#pragma unroll
        for (int off = 16; off > 0; off >>= 1)
            s += __shfl_xor_sync(0xffffffffu, s, off);
        if (lane == 0) out[(size_t)i * 256 + j] = s;
    }
}

// ============================================================
// kfold (fp16 P)
// ============================================================
__global__ __launch_bounds__(128, 1)
void kfold_kernel()
{
    __shared__ float qs[32];
    int i = blockIdx.x >> 3;
    int n = blockIdx.x & 7;
    int tid = threadIdx.x;
    if (tid < 32) qs[tid] = g_qp[i * 256 + n * 32 + tid];
    __syncthreads();

    const __half2* base = (const __half2*)g_P
                        + ((size_t)(n * 32) * 512 + i) * 128 + tid;
    float ax = 0.f, ay = 0.f;
#pragma unroll 8
    for (int jj = 0; jj < 32; jj++) {
        float2 p = __half22float2(base[(size_t)jj * 65536]);
        float s = qs[jj];
        ax += s * p.x; ay += s * p.y;
    }
    const float rs = 0.04419417382415922f;
    ax *= rs; ay *= rs;
    __nv_bfloat16 hx = __float2bfloat16(ax);
    __nv_bfloat16 hy = __float2bfloat16(ay);
    __nv_bfloat16 lx = __float2bfloat16(ax - __bfloat162float(hx));
    __nv_bfloat16 ly = __float2bfloat16(ay - __bfloat162float(hy));
    size_t o = ((size_t)i * NH + n) * 128 + tid;
    ((__nv_bfloat162*)g_a_hi)[o] = __nv_bfloat162(hx, hy);
    ((__nv_bfloat162*)g_a_lo)[o] = __nv_bfloat162(lx, ly);
}

// ============================================================
// flash_part v2 (occ 2): K chunks m=32, V in 4 quarters
// ============================================================
#define FA_A_HI  0
#define FA_A_LO  16896
#define FA_KBUF  33792
#define FA_KSTG  20480
#define FA_VLO   16896
#define FA_P     74752
#define FA_PLO   8704
#define FA_STATS 92160
#define SMEM_FA  93696

__global__ __launch_bounds__(256, 2)
void flash_part()
{
    extern __shared__ char smem[];
    uint32_t sb = smem_u32(smem);
    int tid = threadIdx.x, lane = tid & 31, wid = tid >> 5;
    int wi = wid & 1, wh = wid >> 1;

    int n = blockIdx.x / 40;
    int r = blockIdx.x % 40;
    int b, c;
    if      (r < 4)  { b = r;                c = 0;            }
    else if (r < 12) { b = 4 + (r - 4) / 2;  c = (r - 4) % 2;  }
    else if (r < 24) { b = 8 + (r - 12) / 3; c = (r - 12) % 3; }
    else             { b = 12 + (r - 24) / 4; c = (r - 24) % 4; }
    int i0 = b * 32;
    int t0 = c * 128;
    bool lastc = (c == (b >> 2));

    float* sMaxP = (float*)(smem + FA_STATS);
    float* sSumP = sMaxP + 128;

#pragma unroll
    for (int p = 0; p < 4; p++) {
        int idx = p * 256 + tid;
        int rr = idx >> 5, cc = idx & 31;
        cpa16(sb + FA_A_HI + rr * 528 + cc * 16, g_a_hi + ((size_t)(i0 + rr) * NH + n) * 256 + cc * 8);
        cpa16(sb + FA_A_LO + rr * 528 + cc * 16, g_a_lo + ((size_t)(i0 + rr) * NH + n) * 256 + cc * 8);
    }
    CP_COMMIT();

    auto kload = [&](int mc, int s) {
        uint32_t st = sb + FA_KBUF + s * FA_KSTG;
#pragma unroll
        for (int p = 0; p < 2; p++) {
            int idx = p * 256 + tid;
            int rr = idx >> 2, cc = idx & 3;
            cpa16(st + rr * 80 + cc * 16,         g_k_hi + (t0 + rr) * 256 + mc * 32 + cc * 8);
            cpa16(st + 10240 + rr * 80 + cc * 16, g_k_lo + (t0 + rr) * 256 + mc * 32 + cc * 8);
        }
        CP_COMMIT();
    };
    auto vload = [&](int tq) {
        uint32_t st = sb + FA_KBUF;
#pragma unroll
        for (int p = 0; p < 4; p++) {
            int idx = p * 256 + tid;
            int rr = idx >> 5, cc = idx & 31;
            cpa16(st + rr * 528 + cc * 16,          g_v_hi + (t0 + tq * 32 + rr) * 256 + cc * 8);
            cpa16(st + FA_VLO + rr * 528 + cc * 16, g_v_lo + (t0 + tq * 32 + rr) * 256 + cc * 8);
        }
        CP_COMMIT();
    };

    kload(0, 0);
    kload(1, 1);

    int g = lane >> 2, qq = lane & 3;
    float s[4][4];
#pragma unroll
    for (int nt = 0; nt < 4; nt++)
#pragma unroll
        for (int e = 0; e < 4; e++) s[nt][e] = 0.f;

    for (int mc = 0; mc < 8; mc++) {
        if (mc < 7) CP_WAIT(1); else CP_WAIT(0);
        __syncthreads();
        uint32_t kb = sb + FA_KBUF + (mc & 1) * FA_KSTG;
        uint32_t aH = sb + FA_A_HI + (wi * 16 + (lane & 15)) * 528
                    + (lane >> 4) * 16 + mc * 64;
#pragma unroll
        for (int ks = 0; ks < 2; ks++) {
            uint32_t ah[4], al[4];
            ldsm_x4(ah, aH + ks * 32);
            ldsm_x4(al, aH + (FA_A_LO - FA_A_HI) + ks * 32);
#pragma unroll
            for (int nt = 0; nt < 4; nt++) {
                uint32_t bo = kb + (wh * 32 + nt * 8 + (lane & 7)) * 80
                            + ((lane >> 3) & 1) * 16 + ks * 32;
                uint32_t bh[2], bl[2];
                ldsm_x2(bh, bo);
                ldsm_x2(bl, bo + 10240);
                mma16816(s[nt], ah, bh);
                mma16816(s[nt], ah, bl);
                mma16816(s[nt], al, bh);
            }
        }
        __syncthreads();
        if (mc < 6) kload(mc + 2, mc & 1);
    }

    if (lastc) {
#pragma unroll
        for (int nt = 0; nt < 4; nt++) {
            int tbase = t0 + wh * 32 + nt * 8 + qq * 2;
            int ig0 = i0 + wi * 16 + g, ig1 = ig0 + 8;
            if (tbase     > ig0) s[nt][0] = -1e30f;
            if (tbase + 1 > ig0) s[nt][1] = -1e30f;
            if (tbase     > ig1) s[nt][2] = -1e30f;
            if (tbase + 1 > ig1) s[nt][3] = -1e30f;
        }
    }

    float mx0 = -1e30f, mx1 = -1e30f;
#pragma unroll
    for (int nt = 0; nt < 4; nt++) {
        mx0 = fmaxf(mx0, fmaxf(s[nt][0], s[nt][1]));
        mx1 = fmaxf(mx1, fmaxf(s[nt][2], s[nt][3]));
    }
#pragma unroll
    for (int off = 1; off <= 2; off <<= 1) {
        mx0 = fmaxf(mx0, __shfl_xor_sync(0xffffffffu, mx0, off));
        mx1 = fmaxf(mx1, __shfl_xor_sync(0xffffffffu, mx1, off));
    }
    if (qq == 0) {
        sMaxP[wh * 32 + wi * 16 + g]     = mx0;
        sMaxP[wh * 32 + wi * 16 + g + 8] = mx1;
    }
    __syncthreads();

    int r0 = wi * 16 + g, r1 = r0 + 8;
    float mn0 = fmaxf(fmaxf(sMaxP[r0], sMaxP[32 + r0]),
                      fmaxf(sMaxP[64 + r0], sMaxP[96 + r0]));
    float mn1 = fmaxf(fmaxf(sMaxP[r1], sMaxP[32 + r1]),
                      fmaxf(sMaxP[64 + r1], sMaxP[96 + r1]));

    float sum0 = 0.f, sum1 = 0.f;
#pragma unroll
    for (int nt = 0; nt < 4; nt++) {
        float p0 = __expf(s[nt][0] - mn0);
        float p1 = __expf(s[nt][1] - mn0);
        float p2 = __expf(s[nt][2] - mn1);
        float p3 = __expf(s[nt][3] - mn1);
        sum0 += p0 + p1; sum1 += p2 + p3;
        __nv_bfloat16 h0 = __float2bfloat16(p0), h1 = __float2bfloat16(p1);
        __nv_bfloat16 h2 = __float2bfloat16(p2), h3 = __float2bfloat16(p3);
        __nv_bfloat162 lo01(__float2bfloat16(p0 - __bfloat162float(h0)),
                            __float2bfloat16(p1 - __bfloat162float(h1)));
        __nv_bfloat162 lo23(__float2bfloat16(p2 - __bfloat162float(h2)),
                            __float2bfloat16(p3 - __bfloat162float(h3)));
        uint32_t colb = (wh * 32 + nt * 8 + qq * 2) * 2;
        *(__nv_bfloat162*)(smem + FA_P + r0 * 272 + colb) = __nv_bfloat162(h0, h1);
        *(__nv_bfloat162*)(smem + FA_P + r1 * 272 + colb) = __nv_bfloat162(h2, h3);
        *(__nv_bfloat162*)(smem + FA_P + FA_PLO + r0 * 272 + colb) = lo01;
        *(__nv_bfloat162*)(smem + FA_P + FA_PLO + r1 * 272 + colb) = lo23;
    }
#pragma unroll
    for (int off = 1; off <= 2; off <<= 1) {
        sum0 += __shfl_xor_sync(0xffffffffu, sum0, off);
        sum1 += __shfl_xor_sync(0xffffffffu, sum1, off);
    }
    if (qq == 0) {
        sSumP[wh * 32 + r0] = sum0;
        sSumP[wh * 32 + r1] = sum1;
    }
    __syncthreads();

    int pidx = (n * 16 + b) * 4 + c;
    if (tid < 32) {
        float mn = fmaxf(fmaxf(sMaxP[tid], sMaxP[32 + tid]),
                         fmaxf(sMaxP[64 + tid], sMaxP[96 + tid]));
        float l = sSumP[tid] + sSumP[32 + tid] + sSumP[64 + tid] + sSumP[96 + tid];
        g_pm[pidx * 32 + tid] = mn;
        g_pl[pidx * 32 + tid] = l;
    }
    vload(0);
    __syncthreads();

    float O[8][4];
#pragma unroll
    for (int t = 0; t < 8; t++)
#pragma unroll
        for (int e = 0; e < 4; e++) O[t][e] = 0.f;

    for (int tq = 0; tq < 4; tq++) {
        CP_WAIT(0);
        __syncthreads();
#pragma unroll
        for (int ks = 0; ks < 2; ks++) {
            uint32_t pa = sb + FA_P + (wi * 16 + (lane & 15)) * 272
                        + (lane >> 4) * 16 + tq * 64 + ks * 32;
            uint32_t ph[4], pl[4];
            ldsm_x4(ph, pa);
            ldsm_x4(pl, pa + FA_PLO);
#pragma unroll
            for (int ntp = 0; ntp < 4; ntp++) {
                uint32_t vo = sb + FA_KBUF + (ks * 16 + (lane & 15)) * 528
                            + (wh * 64 + ntp * 16 + (lane >> 4) * 8) * 2;
                uint32_t vh[4], vl[4];
                ldsm_x4t(vh, vo);
                ldsm_x4t(vl, vo + FA_VLO);
                mma16816_2(O[ntp * 2],     ph, vh[0], vh[1]);
                mma16816_2(O[ntp * 2],     ph, vl[0], vl[1]);
                mma16816_2(O[ntp * 2],     pl, vh[0], vh[1]);
                mma16816_2(O[ntp * 2 + 1], ph, vh[2], vh[3]);
                mma16816_2(O[ntp * 2 + 1], ph, vl[2], vl[3]);
                mma16816_2(O[ntp * 2 + 1], pl, vh[2], vh[3]);
            }
        }
        __syncthreads();
        if (tq < 3) vload(tq + 1);
    }

    float* po = g_po + (size_t)pidx * 32 * 256;
#pragma unroll
    for (int knt = 0; knt < 8; knt++) {
        int k = wh * 64 + knt * 8 + qq * 2;
        *(float2*)&po[(size_t)r0 * 256 + k] = make_float2(O[knt][0], O[knt][1]);
        *(float2*)&po[(size_t)r1 * 256 + k] = make_float2(O[knt][2], O[knt][3]);
    }
}

// flash_combine: merge <=4 chunks per (n, b) -> g_w
__global__ __launch_bounds__(256, 1)
void flash_combine()
{
    int bx = blockIdx.x;
    int n = bx >> 4, b = bx & 15;
    int nch = (b >> 2) + 1;
    int tid = threadIdx.x;
    int row = tid >> 3;
    int k0 = (tid & 7) * 32;

    float m = -1e30f;
#pragma unroll 4
    for (int c = 0; c < nch; c++)
        m = fmaxf(m, g_pm[(bx * 4 + c) * 32 + row]);

    float acc[32];
#pragma unroll
    for (int e = 0; e < 32; e++) acc[e] = 0.f;
    float l = 0.f;

    for (int c = 0; c < nch; c++) {
        float f = __expf(g_pm[(bx * 4 + c) * 32 + row] - m);
        l += f * g_pl[(bx * 4 + c) * 32 + row];
        const float4* po = (const float4*)(g_po + ((size_t)(bx * 4 + c) * 32 + row) * 256 + k0);
#pragma unroll
        for (int e = 0; e < 8; e++) {
            float4 v = po[e];
            acc[e * 4 + 0] += f * v.x; acc[e * 4 + 1] += f * v.y;
            acc[e * 4 + 2] += f * v.z; acc[e * 4 + 3] += f * v.w;
        }
    }
    float il = 1.f / l;
    float* wp = g_w + ((size_t)(b * 32 + row) * NH + n) * 256 + k0;
#pragma unroll
    for (int e = 0; e < 8; e++) {
        *(float4*)(wp + e * 4) = make_float4(acc[e * 4 + 0] * il, acc[e * 4 + 1] * il,
                                             acc[e * 4 + 2] * il, acc[e * 4 + 3] * il);
    }
}

// ============================================================
extern "C" void kernel_launch(void* const* d_in, const int* in_sizes, int n_in,
                              void* d_out, int out_size)
{
    const float* q   = (const float*)d_in[0];
    const float* kk  = (const float*)d_in[1];
    const float* vv  = (const float*)d_in[2];
    const float* Wq  = (const float*)d_in[3];
    const float* Wk  = (const float*)d_in[4];
    const float* Wv  = (const float*)d_in[5];
    float* out = (float*)d_out;

    static cudaStream_t sB = nullptr;
    static cudaEvent_t evA = nullptr, evB = nullptr;
    if (!sB) {
        cudaStreamCreateWithFlags(&sB, cudaStreamNonBlocking);
        cudaEventCreateWithFlags(&evA, cudaEventDisableTiming);
        cudaEventCreateWithFlags(&evB, cudaEventDisableTiming);
    }

    cudaFuncSetAttribute(cube_gemm,  cudaFuncAttributeMaxDynamicSharedMemorySize, SMEM_G);
    cudaFuncSetAttribute(flash_part, cudaFuncAttributeMaxDynamicSharedMemorySize, SMEM_FA);

    prep2_kernel<<<256, 256>>>(kk, vv);
    qp_kernel<<<SEQ / 4, 256>>>(q, Wq);
    cube_gemm<<<2048, 256, SMEM_G>>>(Wk, 0);           // Pk cube (fp16)
    cudaEventRecord(evA, 0);
    cudaStreamWaitEvent(sB, evA, 0);
    cube_gemm<<<2048, 256, SMEM_G, sB>>>(Wv, 1);       // Pv cube (fp32) on stream B
    cudaEventRecord(evB, sB);
    kfold_kernel<<<4096, 128>>>();                     // legacy, overlaps gemm2
    flash_part<<<320, 256, SMEM_FA>>>();
    flash_combine<<<128, 256>>>();                     // -> g_w
    cudaStreamWaitEvent(0, evB, 0);
    vfold_kernel<<<4096, 256>>>(out);                  // -> out
}